// round 11
// baseline (speedup 1.0000x reference)
#include <cuda_runtime.h>
#include <cuda_bf16.h>
#include <math_constants.h>
#include <cstdint>

#define D_MODEL   1024
#define N_HEADS   16
#define HEAD_DIM  64
#define BATCH     2
#define SEQ       2048
#define M_TOT     (BATCH * SEQ)   // 4096
#define GK        1024

// ---------------------------------------------------------------------------
// Scratch (no cudaMalloc allowed)
// ---------------------------------------------------------------------------
__device__ __nv_bfloat16 g_xq_h[M_TOT * D_MODEL], g_xq_l[M_TOT * D_MODEL];
__device__ __nv_bfloat16 g_xk_h[M_TOT * D_MODEL], g_xk_l[M_TOT * D_MODEL];
__device__ __nv_bfloat16 g_xv_h[M_TOT * D_MODEL], g_xv_l[M_TOT * D_MODEL];
__device__ __nv_bfloat16 g_wq_h[GK * D_MODEL], g_wq_l[GK * D_MODEL];
__device__ __nv_bfloat16 g_wk_h[GK * D_MODEL], g_wk_l[GK * D_MODEL];
__device__ __nv_bfloat16 g_wv_h[GK * D_MODEL], g_wv_l[GK * D_MODEL];
__device__ __nv_bfloat16 g_wo_h[GK * D_MODEL], g_wo_l[GK * D_MODEL];
__device__ __nv_bfloat16 g_Qh[M_TOT * D_MODEL], g_Ql[M_TOT * D_MODEL];
__device__ __nv_bfloat16 g_Kh[M_TOT * D_MODEL], g_Kl[M_TOT * D_MODEL];
__device__ __nv_bfloat16 g_Vh[M_TOT * D_MODEL], g_Vl[M_TOT * D_MODEL];
__device__ __nv_bfloat16 g_Oh[M_TOT * D_MODEL], g_Ol[M_TOT * D_MODEL];
__device__ unsigned char g_mflag[BATCH * 32 * 32];

// ---------------------------------------------------------------------------
// Helpers
// ---------------------------------------------------------------------------
__device__ __forceinline__ uint32_t smem_to_u32(const void* smem_ptr) {
    uint32_t addr;
    asm("{ .reg .u64 tmp; cvta.to.shared.u64 tmp, %1; cvt.u32.u64 %0, tmp; }"
        : "=r"(addr) : "l"(smem_ptr));
    return addr;
}
__device__ __forceinline__ void ldmx4(uint32_t* r, uint32_t addr) {
    asm volatile("ldmatrix.sync.aligned.m8n8.x4.shared.b16 {%0,%1,%2,%3}, [%4];"
        : "=r"(r[0]), "=r"(r[1]), "=r"(r[2]), "=r"(r[3]) : "r"(addr));
}
__device__ __forceinline__ void ldmx4t(uint32_t* r, uint32_t addr) {
    asm volatile("ldmatrix.sync.aligned.m8n8.x4.trans.shared.b16 {%0,%1,%2,%3}, [%4];"
        : "=r"(r[0]), "=r"(r[1]), "=r"(r[2]), "=r"(r[3]) : "r"(addr));
}
__device__ __forceinline__ void mma_bf16(float* d, const uint32_t* a, const uint32_t* b) {
    asm volatile(
        "mma.sync.aligned.m16n8k16.row.col.f32.bf16.bf16.f32 "
        "{%0,%1,%2,%3}, {%4,%5,%6,%7}, {%8,%9}, {%0,%1,%2,%3};"
        : "+f"(d[0]), "+f"(d[1]), "+f"(d[2]), "+f"(d[3])
        : "r"(a[0]), "r"(a[1]), "r"(a[2]), "r"(a[3]), "r"(b[0]), "r"(b[1]));
}
__device__ __forceinline__ void split_pack(float x, float y, uint32_t& hi, uint32_t& lo) {
    __nv_bfloat162 h = __floats2bfloat162_rn(x, y);
    __nv_bfloat162 l = __floats2bfloat162_rn(x - __low2float(h), y - __high2float(h));
    hi = *reinterpret_cast<uint32_t*>(&h);
    lo = *reinterpret_cast<uint32_t*>(&l);
}
__device__ __forceinline__ void cpa16(uint32_t s, const void* g) {
    asm volatile("cp.async.ca.shared.global [%0], [%1], 16;" :: "r"(s), "l"(g));
}
#define CP_COMMIT() asm volatile("cp.async.commit_group;" ::: "memory")

// ---------------------------------------------------------------------------
// fp32 -> bf16 hi/lo split pre-passes
// ---------------------------------------------------------------------------
__device__ __forceinline__ void split8_store(const float* s, __nv_bfloat16* h,
                                             __nv_bfloat16* l, int i)
{
    float4 f0 = *(const float4*)(s + i);
    float4 f1 = *(const float4*)(s + i + 4);
    float f[8] = {f0.x, f0.y, f0.z, f0.w, f1.x, f1.y, f1.z, f1.w};
    __nv_bfloat162 hh[4], ll[4];
#pragma unroll
    for (int e = 0; e < 4; e++) {
        hh[e] = __floats2bfloat162_rn(f[2 * e], f[2 * e + 1]);
        ll[e] = __floats2bfloat162_rn(f[2 * e]     - __low2float(hh[e]),
                                      f[2 * e + 1] - __high2float(hh[e]));
    }
    *(uint4*)(h + i) = *(uint4*)hh;
    *(uint4*)(l + i) = *(uint4*)ll;
}

__global__ void split3_kernel(const float* s0, const float* s1, const float* s2,
                              __nv_bfloat16* h0, __nv_bfloat16* l0,
                              __nv_bfloat16* h1, __nv_bfloat16* l1,
                              __nv_bfloat16* h2, __nv_bfloat16* l2)
{
    const float* s; __nv_bfloat16 *h, *l;
    if (blockIdx.z == 0)      { s = s0; h = h0; l = l0; }
    else if (blockIdx.z == 1) { s = s1; h = h1; l = l1; }
    else                      { s = s2; h = h2; l = l2; }
    const int i = (blockIdx.x * blockDim.x + threadIdx.x) * 8;
    split8_store(s, h, l, i);
}

__global__ void split4_kernel(const float* s0, const float* s1, const float* s2, const float* s3,
                              __nv_bfloat16* h0, __nv_bfloat16* l0,
                              __nv_bfloat16* h1, __nv_bfloat16* l1,
                              __nv_bfloat16* h2, __nv_bfloat16* l2,
                              __nv_bfloat16* h3, __nv_bfloat16* l3)
{
    const float* s; __nv_bfloat16 *h, *l;
    if (blockIdx.z == 0)      { s = s0; h = h0; l = l0; }
    else if (blockIdx.z == 1) { s = s1; h = h1; l = l1; }
    else if (blockIdx.z == 2) { s = s2; h = h2; l = l2; }
    else                      { s = s3; h = h3; l = l3; }
    const int i = (blockIdx.x * blockDim.x + threadIdx.x) * 8;
    split8_store(s, h, l, i);
}

// ---------------------------------------------------------------------------
// Pipelined bf16 HMMA GEMM core
// ---------------------------------------------------------------------------
#define GSTR 40
#define GROW (GSTR * 2)
#define TILE_B (128 * GSTR * 2)
#define STAGE_B (4 * TILE_B)
#define GEMM_SMEM (2 * STAGE_B)            // 81920 bytes
#define NITER (GK / 32)

template<bool OUT_SPLIT>
__device__ __forceinline__ void gemm_body(
    const __nv_bfloat16* __restrict__ Ah_g, const __nv_bfloat16* __restrict__ Al_g,
    const __nv_bfloat16* __restrict__ Bh_g, const __nv_bfloat16* __restrict__ Bl_g,
    const float* __restrict__ bias, float* __restrict__ Yf,
    __nv_bfloat16* __restrict__ Yh, __nv_bfloat16* __restrict__ Yl,
    char* smc)
{
    const uint32_t smb = smem_to_u32(smc);
    const int tid    = threadIdx.x;
    const int wid    = tid >> 5;
    const int lane   = tid & 31;
    const int warp_m = wid & 1;
    const int warp_n = wid >> 1;
    const int bm = blockIdx.y * 128;
    const int bn = blockIdx.x * 128;

    float acc[4][4][4];
#pragma unroll
    for (int i = 0; i < 4; i++)
#pragma unroll
        for (int j = 0; j < 4; j++)
#pragma unroll
            for (int k = 0; k < 4; k++) acc[i][j][k] = 0.f;

    const int lrow = tid >> 1;
    const int lseg = (tid & 1) * 16;
    const uint32_t so = (uint32_t)(lrow * GSTR + lseg) * 2;
    const __nv_bfloat16* Ahp = Ah_g + (size_t)(bm + lrow) * GK + lseg;
    const __nv_bfloat16* Alp = Al_g + (size_t)(bm + lrow) * GK + lseg;
    const __nv_bfloat16* Bhp = Bh_g + (size_t)(bn + lrow) * GK + lseg;
    const __nv_bfloat16* Blp = Bl_g + (size_t)(bn + lrow) * GK + lseg;

    const uint32_t a_off = ((uint32_t)(lane & 15) * GSTR + (uint32_t)(lane >> 4) * 8) * 2
                         + (uint32_t)(warp_m * 64) * GROW;
    const uint32_t b_off4 = (uint32_t)((lane & 7) + ((lane >> 4) << 3) + warp_n * 32) * GROW
                          + (uint32_t)((lane >> 3) & 1) * 16;

    auto stage = [&](int buf, int kc) {
        const uint32_t base = smb + buf * STAGE_B + so;
        cpa16(base,                   Ahp + kc);
        cpa16(base + 16,              Ahp + kc + 8);
        cpa16(base + TILE_B,          Alp + kc);
        cpa16(base + TILE_B + 16,     Alp + kc + 8);
        cpa16(base + 2 * TILE_B,      Bhp + kc);
        cpa16(base + 2 * TILE_B + 16, Bhp + kc + 8);
        cpa16(base + 3 * TILE_B,      Blp + kc);
        cpa16(base + 3 * TILE_B + 16, Blp + kc + 8);
    };

    stage(0, 0);
    CP_COMMIT();

    for (int it = 0; it < NITER; it++) {
        if (it + 1 < NITER) {
            stage((it + 1) & 1, (it + 1) * 32);
            CP_COMMIT();
            asm volatile("cp.async.wait_group 1;" ::: "memory");
        } else {
            asm volatile("cp.async.wait_group 0;" ::: "memory");
        }
        __syncthreads();

        const uint32_t AhB = smb + (it & 1) * STAGE_B;
        const uint32_t AlB = AhB + TILE_B;
        const uint32_t BhB = AhB + 2 * TILE_B;
        const uint32_t BlB = AhB + 3 * TILE_B;

#pragma unroll
        for (int ks = 0; ks < 2; ks++) {
            const uint32_t ko = (uint32_t)(ks * 32);
            uint32_t ah[4][4], al[4][4];
#pragma unroll
            for (int am = 0; am < 4; am++) {
                const uint32_t o = a_off + (uint32_t)(am * 16) * GROW + ko;
                ldmx4(ah[am], AhB + o);
                ldmx4(al[am], AlB + o);
            }
            uint32_t bh[2][4], bl[2][4];
#pragma unroll
            for (int p2 = 0; p2 < 2; p2++) {
                const uint32_t o = b_off4 + (uint32_t)(p2 * 16) * GROW + ko;
                ldmx4(bh[p2], BhB + o);
                ldmx4(bl[p2], BlB + o);
            }
#pragma unroll
            for (int am = 0; am < 4; am++)
#pragma unroll
                for (int an = 0; an < 4; an++) {
                    const uint32_t* bhp = bh[an >> 1] + (an & 1) * 2;
                    const uint32_t* blp = bl[an >> 1] + (an & 1) * 2;
                    mma_bf16(acc[am][an], ah[am], bhp);
                    mma_bf16(acc[am][an], ah[am], blp);
                    mma_bf16(acc[am][an], al[am], bhp);
                }
        }
        __syncthreads();
    }

    const int gr = lane >> 2;
    const int gc = (lane & 3) * 2;
#pragma unroll
    for (int am = 0; am < 4; am++) {
#pragma unroll
        for (int an = 0; an < 4; an++) {
            const int row = bm + warp_m * 64 + am * 16 + gr;
            const int col = bn + warp_n * 32 + an * 8 + gc;
            const float b0 = __ldg(&bias[col]);
            const float b1 = __ldg(&bias[col + 1]);
            const float y00 = acc[am][an][0] + b0, y01 = acc[am][an][1] + b1;
            const float y10 = acc[am][an][2] + b0, y11 = acc[am][an][3] + b1;
            if (OUT_SPLIT) {
                uint32_t h0, l0, h1, l1;
                split_pack(y00, y01, h0, l0);
                split_pack(y10, y11, h1, l1);
                *(uint32_t*)&Yh[(size_t)row * D_MODEL + col]       = h0;
                *(uint32_t*)&Yl[(size_t)row * D_MODEL + col]       = l0;
                *(uint32_t*)&Yh[(size_t)(row + 8) * D_MODEL + col] = h1;
                *(uint32_t*)&Yl[(size_t)(row + 8) * D_MODEL + col] = l1;
            } else {
                *(float2*)&Yf[(size_t)row * D_MODEL + col]       = make_float2(y00, y01);
                *(float2*)&Yf[(size_t)(row + 8) * D_MODEL + col] = make_float2(y10, y11);
            }
        }
    }
}

__global__ __launch_bounds__(256, 2) void gemm_qkv_kernel(
    const __nv_bfloat16* xqh, const __nv_bfloat16* xql,
    const __nv_bfloat16* xkh, const __nv_bfloat16* xkl,
    const __nv_bfloat16* xvh, const __nv_bfloat16* xvl,
    const __nv_bfloat16* wqh, const __nv_bfloat16* wql,
    const __nv_bfloat16* wkh, const __nv_bfloat16* wkl,
    const __nv_bfloat16* wvh, const __nv_bfloat16* wvl,
    const float* bq, const float* bk, const float* bv,
    __nv_bfloat16* Qh, __nv_bfloat16* Ql,
    __nv_bfloat16* Kh, __nv_bfloat16* Kl,
    __nv_bfloat16* Vh, __nv_bfloat16* Vl)
{
    extern __shared__ char smc[];
    const __nv_bfloat16 *Ah, *Al, *Bh, *Bl;
    const float* bias;
    __nv_bfloat16 *Yh, *Yl;
    if (blockIdx.z == 0) { Ah=xqh; Al=xql; Bh=wqh; Bl=wql; bias=bq; Yh=Qh; Yl=Ql; }
    else if (blockIdx.z == 1) { Ah=xkh; Al=xkl; Bh=wkh; Bl=wkl; bias=bk; Yh=Kh; Yl=Kl; }
    else { Ah=xvh; Al=xvl; Bh=wvh; Bl=wvl; bias=bv; Yh=Vh; Yl=Vl; }
    gemm_body<true>(Ah, Al, Bh, Bl, bias, nullptr, Yh, Yl, smc);
}

__global__ __launch_bounds__(256, 2) void gemm_out_kernel(
    const __nv_bfloat16* Ah, const __nv_bfloat16* Al,
    const __nv_bfloat16* Bh, const __nv_bfloat16* Bl,
    const float* bias, float* Yf)
{
    extern __shared__ char smc[];
    gemm_body<false>(Ah, Al, Bh, Bl, bias, Yf, nullptr, nullptr, smc);
}

// ---------------------------------------------------------------------------
// Mask tile flag pre-pass (64x64 granularity)
// ---------------------------------------------------------------------------
__global__ __launch_bounds__(128) void mask_flags_kernel(
    const int* __restrict__ mask, unsigned char* __restrict__ flags)
{
    const int kt = blockIdx.x, qt = blockIdx.y, b = blockIdx.z;
    const int tid = threadIdx.x;
    const int row = tid >> 1;
    const int cs  = (tid & 1) * 32;
    const int* p = mask + (size_t)(b * SEQ + qt * 64 + row) * SEQ + kt * 64 + cs;
    int ok = 1;
#pragma unroll
    for (int u = 0; u < 8; u++) {
        int4 v = *(const int4*)(p + 4 * u);
        ok = ok && v.x && v.y && v.z && v.w;
    }
    __shared__ int s_all;
    if (tid == 0) s_all = 1;
    __syncthreads();
    if (!ok) atomicAnd(&s_all, 0);
    __syncthreads();
    if (tid == 0) flags[(b * 32 + qt) * 32 + kt] = (unsigned char)s_all;
}

// ---------------------------------------------------------------------------
// HMMA flash attention: CTA = 128 q-rows, 4 warps x 32 q-rows (2 m16 groups).
// Q frags held in registers; K/V double-buffered cp.async; K/V frags shared
// across both q-groups (MMA:LDSM = 6).
// ---------------------------------------------------------------------------
#define AROW 144                          // bytes per 64-col row (72 halves)
#define OFF_QL (128 * AROW)               // Ql after Qh (128 rows each)
#define OFF_KV (2 * 128 * AROW)           // 36864
#define KV_STG (4 * 64 * AROW)            // Kh,Kl,Vh,Vl (64 rows each) = 36864
#define ATTN_SMEM_BYTES (OFF_KV + 2 * KV_STG)   // 110592

__global__ __launch_bounds__(128, 2) void flash_attn_mma_kernel(
    const __nv_bfloat16* __restrict__ Qh_g, const __nv_bfloat16* __restrict__ Ql_g,
    const __nv_bfloat16* __restrict__ Kh_g, const __nv_bfloat16* __restrict__ Kl_g,
    const __nv_bfloat16* __restrict__ Vh_g, const __nv_bfloat16* __restrict__ Vl_g,
    const int* __restrict__ mask, const unsigned char* __restrict__ flags,
    __nv_bfloat16* __restrict__ Oh_g, __nv_bfloat16* __restrict__ Ol_g)
{
    extern __shared__ char sm[];
    const uint32_t smb = smem_to_u32(sm);

    const int tid  = threadIdx.x;
    const int w    = tid >> 5;
    const int lane = tid & 31;
    const int qt = blockIdx.x, h = blockIdx.y, b = blockIdx.z;
    const int qbase = qt * 128;
    const float scale = 0.125f;

    // ---- Q tile stage: thread t -> row t (128B hi + 128B lo) ----
    {
        const size_t go = (size_t)(b * SEQ + qbase + tid) * D_MODEL + h * HEAD_DIM;
        const uint32_t qs = smb + (uint32_t)(tid * AROW);
#pragma unroll
        for (int u = 0; u < 4; u++) {
            cpa16(qs + 16 * u,           Qh_g + go + 8 * u);
            cpa16(qs + 64 + 16 * u,      Qh_g + go + 32 + 8 * u);
            cpa16(qs + OFF_QL + 16 * u,      Ql_g + go + 8 * u);
            cpa16(qs + OFF_QL + 64 + 16 * u, Ql_g + go + 32 + 8 * u);
        }
        CP_COMMIT();
        asm volatile("cp.async.wait_group 0;" ::: "memory");
    }
    __syncthreads();

    // ---- Q frags in registers (2 groups x 4 k-steps x hi/lo) ----
    uint32_t qh[2][4][4], ql[2][4][4];
#pragma unroll
    for (int g = 0; g < 2; g++) {
        const uint32_t ao = (uint32_t)((w * 32 + g * 16 + (lane & 15)) * AROW
                                       + (lane >> 4) * 16);
#pragma unroll
        for (int kk = 0; kk < 4; kk++) {
            ldmx4(qh[g][kk], smb + ao + kk * 32);
            ldmx4(ql[g][kk], smb + OFF_QL + ao + kk * 32);
        }
    }
    __syncthreads();   // Q smem no longer needed (frags in regs)

    float accO[2][8][4];
#pragma unroll
    for (int g = 0; g < 2; g++)
#pragma unroll
        for (int t = 0; t < 8; t++)
#pragma unroll
            for (int i = 0; i < 4; i++) accO[g][t][i] = 0.f;
    float mrw[2][2], lrw[2][2];
#pragma unroll
    for (int g = 0; g < 2; g++) { mrw[g][0] = mrw[g][1] = -1e30f; lrw[g][0] = lrw[g][1] = 0.f; }

    // KV staging map: thread t -> row t>>1, 64B segment (t&1)
    const int lrow = tid >> 1;
    const uint32_t stg = (uint32_t)(lrow * AROW + (tid & 1) * 64);
    const int gseg = (tid & 1) * 32;

    auto stage_kv = [&](int buf, int kt) {
        const uint32_t base = smb + OFF_KV + buf * KV_STG + stg;
        const size_t go = (size_t)(b * SEQ + kt + lrow) * D_MODEL + h * HEAD_DIM + gseg;
#pragma unroll
        for (int u = 0; u < 4; u++) {
            cpa16(base + 16 * u,                 Kh_g + go + 8 * u);
            cpa16(base + 64 * AROW + 16 * u,     Kl_g + go + 8 * u);
            cpa16(base + 128 * AROW + 16 * u,    Vh_g + go + 8 * u);
            cpa16(base + 192 * AROW + 16 * u,    Vl_g + go + 8 * u);
        }
    };

    const uint32_t k_off = (uint32_t)((((lane >> 4) << 3) + (lane & 7)) * AROW
                                      + ((lane >> 3) & 1) * 16);
    const uint32_t v_off = (uint32_t)(((((lane >> 3) & 1) * 8 + (lane & 7)) * AROW)
                                      + ((lane >> 4) << 4));
    // per-warp mask-flag row (warps 0,1 -> first 64 q; 2,3 -> second)
    const unsigned char* fp = flags + (size_t)(b * 32 + 2 * qt + (w >> 1)) * 32;

    stage_kv(0, 0);
    CP_COMMIT();

    for (int it = 0; it < 32; it++) {
        if (it + 1 < 32) {
            stage_kv((it + 1) & 1, (it + 1) * 64);
            CP_COMMIT();
            asm volatile("cp.async.wait_group 1;" ::: "memory");
        } else {
            asm volatile("cp.async.wait_group 0;" ::: "memory");
        }
        __syncthreads();

        const uint32_t KhB = smb + OFF_KV + (it & 1) * KV_STG;
        const uint32_t KlB = KhB + 64 * AROW;
        const uint32_t VhB = KhB + 128 * AROW;
        const uint32_t VlB = KhB + 192 * AROW;

        // ---- S = Q K^T for both groups (K frags loaded once) ----
        float s[2][8][4];
#pragma unroll
        for (int g = 0; g < 2; g++)
#pragma unroll
            for (int t = 0; t < 8; t++)
#pragma unroll
                for (int i = 0; i < 4; i++) s[g][t][i] = 0.f;

#pragma unroll
        for (int kk = 0; kk < 4; kk++) {
#pragma unroll
            for (int p = 0; p < 4; p++) {
                uint32_t bh[4], bl[4];
                const uint32_t o = k_off + (uint32_t)(p * 16) * AROW + kk * 32;
                ldmx4(bh, KhB + o);
                ldmx4(bl, KlB + o);
#pragma unroll
                for (int g = 0; g < 2; g++) {
                    mma_bf16(s[g][2 * p],     qh[g][kk], bh);
                    mma_bf16(s[g][2 * p],     qh[g][kk], bl);
                    mma_bf16(s[g][2 * p],     ql[g][kk], bh);
                    mma_bf16(s[g][2 * p + 1], qh[g][kk], bh + 2);
                    mma_bf16(s[g][2 * p + 1], qh[g][kk], bl + 2);
                    mma_bf16(s[g][2 * p + 1], ql[g][kk], bh + 2);
                }
            }
        }

        // ---- mask + scale ----
        if (__ldg(fp + it)) {
#pragma unroll
            for (int g = 0; g < 2; g++)
#pragma unroll
                for (int t = 0; t < 8; t++) {
                    s[g][t][0] *= scale; s[g][t][1] *= scale;
                    s[g][t][2] *= scale; s[g][t][3] *= scale;
                }
        } else {
#pragma unroll
            for (int g = 0; g < 2; g++) {
                const int mr = qbase + w * 32 + g * 16 + (lane >> 2);
                const int* mp0 = mask + (size_t)(b * SEQ + mr) * SEQ + it * 64 + 2 * (lane & 3);
                const int* mp1 = mp0 + 8 * SEQ;
#pragma unroll
                for (int t = 0; t < 8; t++) {
                    int2 m0 = *(const int2*)(mp0 + 8 * t);
                    int2 m1 = *(const int2*)(mp1 + 8 * t);
                    s[g][t][0] = m0.x ? s[g][t][0] * scale : -1e30f;
                    s[g][t][1] = m0.y ? s[g][t][1] * scale : -1e30f;
                    s[g][t][2] = m1.x ? s[g][t][2] * scale : -1e30f;
                    s[g][t][3] = m1.y ? s[g][t][3] * scale : -1e30f;
                }
            }
        }

        // ---- online softmax per group ----
#pragma unroll
        for (int g = 0; g < 2; g++) {
            float mx0 = -1e30f, mx1 = -1e30f;
#pragma unroll
            for (int t = 0; t < 8; t++) {
                mx0 = fmaxf(mx0, fmaxf(s[g][t][0], s[g][t][1]));
                mx1 = fmaxf(mx1, fmaxf(s[g][t][2], s[g][t][3]));
            }
            mx0 = fmaxf(mx0, __shfl_xor_sync(0xffffffffu, mx0, 1));
            mx0 = fmaxf(mx0, __shfl_xor_sync(0xffffffffu, mx0, 2));
            mx1 = fmaxf(mx1, __shfl_xor_sync(0xffffffffu, mx1, 1));
            mx1 = fmaxf(mx1, __shfl_xor_sync(0xffffffffu, mx1, 2));

            const float mn0 = fmaxf(mrw[g][0], mx0);
            const float mn1 = fmaxf(mrw[g][1], mx1);
            const float a0 = __expf(mrw[g][0] - mn0);
            const float a1 = __expf(mrw[g][1] - mn1);
            mrw[g][0] = mn0; mrw[g][1] = mn1;

            float sum0 = 0.f, sum1 = 0.f;
#pragma unroll
            for (int t = 0; t < 8; t++) {
                s[g][t][0] = __expf(s[g][t][0] - mn0);
                s[g][t][1] = __expf(s[g][t][1] - mn0);
                s[g][t][2] = __expf(s[g][t][2] - mn1);
                s[g][t][3] = __expf(s[g][t][3] - mn1);
                sum0 += s[g][t][0] + s[g][t][1];
                sum1 += s[g][t][2] + s[g][t][3];
            }
            sum0 += __shfl_xor_sync(0xffffffffu, sum0, 1);
            sum0 += __shfl_xor_sync(0xffffffffu, sum0, 2);
            sum1 += __shfl_xor_sync(0xffffffffu, sum1, 1);
            sum1 += __shfl_xor_sync(0xffffffffu, sum1, 2);
            lrw[g][0] = lrw[g][0] * a0 + sum0;
            lrw[g][1] = lrw[g][1] * a1 + sum1;

#pragma unroll
            for (int t = 0; t < 8; t++) {
                accO[g][t][0] *= a0; accO[g][t][1] *= a0;
                accO[g][t][2] *= a1; accO[g][t][3] *= a1;
            }
        }

        // ---- O += P V for both groups (V frags loaded once) ----
#pragma unroll
        for (int kk = 0; kk < 4; kk++) {
            uint32_t pah[2][4], pal[2][4];
#pragma unroll
            for (int g = 0; g < 2; g++) {
                split_pack(s[g][2 * kk][0],     s[g][2 * kk][1],     pah[g][0], pal[g][0]);
                split_pack(s[g][2 * kk][2],     s[g][2 * kk][3],     pah[g][1], pal[g][1]);
                split_pack(s[g][2 * kk + 1][0], s[g][2 * kk + 1][1], pah[g][2], pal[g][2]);
                split_pack(s[g][2 * kk + 1][2], s[g][2 * kk + 1][3], pah[g][3], pal[g][3]);
            }
#pragma unroll
            for (int jp = 0; jp < 4; jp++) {
                uint32_t vh[4], vl[4];
                const uint32_t o = v_off + (uint32_t)(kk * 16) * AROW + jp * 32;
                ldmx4t(vh, VhB + o);
                ldmx4t(vl, VlB + o);
#pragma unroll
                for (int g = 0; g < 2; g++) {
                    mma_bf16(accO[g][2 * jp],     pah[g], vh);
                    mma_bf16(accO[g][2 * jp],     pah[g], vl);
                    mma_bf16(accO[g][2 * jp],     pal[g], vh);
                    mma_bf16(accO[g][2 * jp + 1], pah[g], vh + 2);
                    mma_bf16(accO[g][2 * jp + 1], pah[g], vl + 2);
                    mma_bf16(accO[g][2 * jp + 1], pal[g], vh + 2);
                }
            }
        }
        __syncthreads();
    }

    // ---- epilogue: normalize, split, store bf16 hi/lo ----
#pragma unroll
    for (int g = 0; g < 2; g++) {
        const float inv0 = 1.0f / lrw[g][0];
        const float inv1 = 1.0f / lrw[g][1];
        const int q0 = qbase + w * 32 + g * 16 + (lane >> 2);
        const size_t bo0 = (size_t)(b * SEQ + q0) * D_MODEL + h * HEAD_DIM + 2 * (lane & 3);
        const size_t bo1 = bo0 + 8 * D_MODEL;
#pragma unroll
        for (int t = 0; t < 8; t++) {
            uint32_t h0, l0, h1, l1;
            split_pack(accO[g][t][0] * inv0, accO[g][t][1] * inv0, h0, l0);
            split_pack(accO[g][t][2] * inv1, accO[g][t][3] * inv1, h1, l1);
            *(uint32_t*)&Oh_g[bo0 + 8 * t] = h0;
            *(uint32_t*)&Ol_g[bo0 + 8 * t] = l0;
            *(uint32_t*)&Oh_g[bo1 + 8 * t] = h1;
            *(uint32_t*)&Ol_g[bo1 + 8 * t] = l1;
        }
    }
}

// ---------------------------------------------------------------------------
// Launcher — inputs: query key value mask wq bq wk bk wv bv wo bo
// ---------------------------------------------------------------------------
extern "C" void kernel_launch(void* const* d_in, const int* in_sizes, int n_in,
                              void* d_out, int out_size)
{
    const float* query = (const float*)d_in[0];
    const float* key   = (const float*)d_in[1];
    const float* value = (const float*)d_in[2];
    const int*   mask  = (const int*)  d_in[3];
    const float* wq    = (const float*)d_in[4];
    const float* bq    = (const float*)d_in[5];
    const float* wk    = (const float*)d_in[6];
    const float* bk    = (const float*)d_in[7];
    const float* wv    = (const float*)d_in[8];
    const float* bv    = (const float*)d_in[9];
    const float* wo    = (const float*)d_in[10];
    const float* bo    = (const float*)d_in[11];
    float* out = (float*)d_out;

    __nv_bfloat16 *xqh, *xql, *xkh, *xkl, *xvh, *xvl;
    __nv_bfloat16 *wqh, *wql, *wkh, *wkl, *wvh, *wvl, *woh, *wol;
    __nv_bfloat16 *Qh, *Ql, *Kh, *Kl, *Vh, *Vl, *Oh, *Ol;
    unsigned char* Fl;
    cudaGetSymbolAddress((void**)&xqh, g_xq_h); cudaGetSymbolAddress((void**)&xql, g_xq_l);
    cudaGetSymbolAddress((void**)&xkh, g_xk_h); cudaGetSymbolAddress((void**)&xkl, g_xk_l);
    cudaGetSymbolAddress((void**)&xvh, g_xv_h); cudaGetSymbolAddress((void**)&xvl, g_xv_l);
    cudaGetSymbolAddress((void**)&wqh, g_wq_h); cudaGetSymbolAddress((void**)&wql, g_wq_l);
    cudaGetSymbolAddress((void**)&wkh, g_wk_h); cudaGetSymbolAddress((void**)&wkl, g_wk_l);
    cudaGetSymbolAddress((void**)&wvh, g_wv_h); cudaGetSymbolAddress((void**)&wvl, g_wv_l);
    cudaGetSymbolAddress((void**)&woh, g_wo_h); cudaGetSymbolAddress((void**)&wol, g_wo_l);
    cudaGetSymbolAddress((void**)&Qh, g_Qh); cudaGetSymbolAddress((void**)&Ql, g_Ql);
    cudaGetSymbolAddress((void**)&Kh, g_Kh); cudaGetSymbolAddress((void**)&Kl, g_Kl);
    cudaGetSymbolAddress((void**)&Vh, g_Vh); cudaGetSymbolAddress((void**)&Vl, g_Vl);
    cudaGetSymbolAddress((void**)&Oh, g_Oh); cudaGetSymbolAddress((void**)&Ol, g_Ol);
    cudaGetSymbolAddress((void**)&Fl, g_mflag);

    cudaFuncSetAttribute(flash_attn_mma_kernel,
                         cudaFuncAttributeMaxDynamicSharedMemorySize, ATTN_SMEM_BYTES);
    cudaFuncSetAttribute(gemm_qkv_kernel,
                         cudaFuncAttributeMaxDynamicSharedMemorySize, GEMM_SMEM);
    cudaFuncSetAttribute(gemm_out_kernel,
                         cudaFuncAttributeMaxDynamicSharedMemorySize, GEMM_SMEM);

    // ---- pre-passes ----
    dim3 gf(32, 32, BATCH);
    mask_flags_kernel<<<gf, 128>>>(mask, Fl);
    dim3 g3(M_TOT * D_MODEL / (8 * 256), 1, 3);
    split3_kernel<<<g3, 256>>>(query, key, value, xqh, xql, xkh, xkl, xvh, xvl);
    dim3 g4(GK * D_MODEL / (8 * 256), 1, 4);
    split4_kernel<<<g4, 256>>>(wq, wk, wv, wo, wqh, wql, wkh, wkl, wvh, wvl, woh, wol);

    // ---- QKV projections: one merged launch ----
    dim3 gq(D_MODEL / 128, M_TOT / 128, 3);   // (8, 32, 3) = 768 CTAs
    gemm_qkv_kernel<<<gq, 256, GEMM_SMEM>>>(
        xqh, xql, xkh, xkl, xvh, xvl,
        wqh, wql, wkh, wkl, wvh, wvl,
        bq, bk, bv, Qh, Ql, Kh, Kl, Vh, Vl);

    // ---- attention ----
    dim3 ga(SEQ / 128, N_HEADS, BATCH);    // (16, 16, 2) = 512 CTAs
    flash_attn_mma_kernel<<<ga, 128, ATTN_SMEM_BYTES>>>(
        Qh, Ql, Kh, Kl, Vh, Vl, mask, Fl, Oh, Ol);

    // ---- output projection ----
    dim3 gg(D_MODEL / 128, M_TOT / 128);   // (8, 32)
    gemm_out_kernel<<<gg, 256, GEMM_SMEM>>>(Oh, Ol, woh, wol, bo, out);
}